// round 10
// baseline (speedup 1.0000x reference)
#include <cuda_runtime.h>
#include <cuda_fp16.h>
#include <cstdint>

// QuantizedLinear on GB300 (sm_103a harness, compute_103 virtual arch -> legacy
// mma.sync.m16n8k16 path; tcgen05 PTX rejected by ptxas at this target).
//   y[b,o] = scale[o] * sum_k x[b,k] * (q[o,k] - 8)
//
// Round 10: R8 GEMM skeleton (KC=64, 3 stages, 4 warps @ 64x64, SW128 rows,
// one barrier/chunk, 2 CTAs/SM) + in-GEMM W dequant with WARP-COALESCED
// packed loads (8 lanes share one 128B line -> 8 wavefronts, fixing R9's
// 32-wavefront pattern). No W prepass: saves 268 MB of DRAM traffic.
// Prep = x->fp16 only (8 MB).

static constexpr int M_DIM = 512;
static constexpr int N_DIM = 8192;
static constexpr int K_DIM = 8192;
static constexpr int KWORDS = K_DIM / 2;           // packed words per W row

static constexpr int BM = 128;
static constexpr int BN = 128;
static constexpr int KC = 64;
static constexpr int STAGES = 3;
static constexpr int NCHUNK = K_DIM / KC;          // 128
static constexpr int NTHREADS = 128;               // 4 warps, 2x2 of 64x64

static constexpr int A_BYTES = BM * 128;           // 16 KB (fp16 SW128)
static constexpr int B_BYTES = BN * 128;           // 16 KB (fp16 SW128)
static constexpr int STAGE_BYTES = A_BYTES + B_BYTES;      // 32 KB
static constexpr int SMEM_BYTES  = STAGES * STAGE_BYTES;   // 96 KB

static constexpr int XCONV_BLOCKS = (M_DIM * K_DIM / 4) / 256;   // 4096

// -------- scratch (device global; no runtime allocation) --------
__device__ __align__(16) __half g_xh[(size_t)M_DIM * K_DIM];     // 8 MB

// ---------------- helpers ----------------
__device__ __forceinline__ uint32_t smem_u32(const void* p) {
    uint32_t a;
    asm("{ .reg .u64 t; cvta.to.shared.u64 t, %1; cvt.u32.u64 %0, t; }"
        : "=r"(a) : "l"(p));
    return a;
}

__device__ __forceinline__ uint32_t sw128(uint32_t off) {
    return off ^ ((off >> 3) & 0x70u);
}

// (1024+q) - 1032 = q - 8, exact in fp16, both lanes
__device__ __forceinline__ uint32_t dq_sub(uint32_t v) {
    uint32_t r;
    asm("sub.rn.f16x2 %0, %1, %2;" : "=r"(r) : "r"(v), "r"(0x64086408u));
    return r;
}

// packed word (low byte = 2 nibbles) -> fp16x2 {low=even k (hi nibble),
// high=odd k (lo nibble)}, value q-8, exact
__device__ __forceinline__ uint32_t dqw(uint32_t w) {
    uint32_t t = ((w >> 4) & 0xFu) | 0x64006400u;
    t |= (w << 16) & 0x000F0000u;
    return dq_sub(t);
}

__device__ __forceinline__ void cp_async16(uint32_t dst, const void* src) {
    asm volatile("cp.async.cg.shared.global [%0], [%1], 16;"
                 :: "r"(dst), "l"(src) : "memory");
}
__device__ __forceinline__ void cp_commit() {
    asm volatile("cp.async.commit_group;" ::: "memory");
}
template <int N>
__device__ __forceinline__ void cp_wait() {
    asm volatile("cp.async.wait_group %0;" :: "n"(N) : "memory");
}

__device__ __forceinline__ void ldmatrix4(uint32_t& r0, uint32_t& r1,
                                          uint32_t& r2, uint32_t& r3,
                                          uint32_t addr) {
    asm volatile("ldmatrix.sync.aligned.m8n8.x4.shared.b16 {%0,%1,%2,%3}, [%4];"
                 : "=r"(r0), "=r"(r1), "=r"(r2), "=r"(r3) : "r"(addr));
}

__device__ __forceinline__ void hmma(float* d,
                                     uint32_t a0, uint32_t a1, uint32_t a2, uint32_t a3,
                                     uint32_t b0, uint32_t b1) {
    asm volatile(
        "mma.sync.aligned.m16n8k16.row.col.f32.f16.f16.f32 "
        "{%0,%1,%2,%3}, {%4,%5,%6,%7}, {%8,%9}, {%0,%1,%2,%3};"
        : "+f"(d[0]), "+f"(d[1]), "+f"(d[2]), "+f"(d[3])
        : "r"(a0), "r"(a1), "r"(a2), "r"(a3), "r"(b0), "r"(b1));
}

// ---------------- prepass: x f32 -> fp16 ----------------
__global__ void prep_kernel(const float* __restrict__ x) {
    int i = blockIdx.x * blockDim.x + threadIdx.x;      // float4 index
    float4 v = reinterpret_cast<const float4*>(x)[i];
    reinterpret_cast<__half2*>(g_xh)[2 * i + 0] = __floats2half2_rn(v.x, v.y);
    reinterpret_cast<__half2*>(g_xh)[2 * i + 1] = __floats2half2_rn(v.z, v.w);
}

// ---------------- HMMA GEMM with in-kernel W dequant ----------------
__global__ __launch_bounds__(NTHREADS, 2)
void qgemm_kernel(const int* __restrict__ packed,
                  const float* __restrict__ scale, float* __restrict__ y) {
    extern __shared__ __align__(1024) char sb[];
    const uint32_t sb32 = smem_u32(sb);

    const int tid = threadIdx.x;
    const int wid = tid >> 5;
    const int lid = tid & 31;
    const int N0 = blockIdx.x * BN;
    const int M0 = blockIdx.y * BM;

    const int wm = wid >> 1;            // 0..1 : m offset wm*64
    const int wn = wid & 1;             // 0..1 : n offset wn*64

    const __half* xb = g_xh + (size_t)M0 * K_DIM;
    const unsigned* wpk = reinterpret_cast<const unsigned*>(packed);

    // B producer mapping (coalesced): seg = tid + i*128, n = seg>>3, j = seg&7
    // gmem: row N0+n, 16B at word offset (k0>>1) + j*4 (8 lanes -> one 128B line)
    const int bn = tid >> 3;            // base row (for i=0); rows advance by 16
    const int bj = tid & 7;

    float acc[4][8][4];
    #pragma unroll
    for (int i = 0; i < 4; i++)
        #pragma unroll
        for (int j = 0; j < 8; j++)
            #pragma unroll
            for (int v = 0; v < 4; v++)
                acc[i][j][v] = 0.0f;

    // ---- prologue: stages 0..S-2 <- chunks 0..S-2 ----
    #pragma unroll
    for (int s = 0; s < STAGES - 1; s++) {
        const int k0 = s * KC;
        const uint32_t As = sb32 + s * STAGE_BYTES;
        const uint32_t Bso = (uint32_t)(s * STAGE_BYTES + A_BYTES);
        #pragma unroll
        for (int i = 0; i < 8; i++) {                   // A: 1024 segs
            int seg = tid + i * NTHREADS;
            int m = seg >> 3, j = seg & 7;
            cp_async16(As + sw128((uint32_t)(m * 128 + j * 16)),
                       xb + (size_t)m * K_DIM + k0 + j * 8);
        }
        cp_commit();
        // B: coalesced LDG packed -> dequant -> STS (prologue: eager)
        #pragma unroll
        for (int i = 0; i < 8; i++) {
            int n = bn + i * 16;
            uint4 p = *reinterpret_cast<const uint4*>(
                wpk + (size_t)(N0 + n) * KWORDS + (k0 >> 1) + bj * 4);
            uint4 q;
            q.x = dqw(p.x); q.y = dqw(p.y); q.z = dqw(p.z); q.w = dqw(p.w);
            *reinterpret_cast<uint4*>(sb + Bso +
                sw128((uint32_t)(n * 128 + bj * 16))) = q;
        }
    }

    const uint32_t a_warp = (uint32_t)(wm * 64 * 128);
    const uint32_t b_warp = (uint32_t)(wn * 64 * 128);
    const int ql = lid >> 3;            // 0..3
    const int qr = lid & 7;

    for (int c = 0; c < NCHUNK; c++) {
        cp_wait<STAGES - 2>();
        __syncthreads();

        // ---- loads for chunk c+S-1 into stage (c-1)%S (freed by barrier above) ----
        const int fc = c + STAGES - 1;
        const bool fetch = (fc < NCHUNK);
        uint4 bp[8];
        uint32_t fB = 0;
        if (fetch) {
            const int fst = fc % STAGES;
            const int k0 = fc * KC;
            const uint32_t As = sb32 + fst * STAGE_BYTES;
            fB = (uint32_t)(fst * STAGE_BYTES + A_BYTES);
            // B LDGs first (longest latency; MLP=8, hidden under compute)
            #pragma unroll
            for (int i = 0; i < 8; i++) {
                int n = bn + i * 16;
                bp[i] = *reinterpret_cast<const uint4*>(
                    wpk + (size_t)(N0 + n) * KWORDS + (k0 >> 1) + bj * 4);
            }
            #pragma unroll
            for (int i = 0; i < 8; i++) {
                int seg = tid + i * NTHREADS;
                int m = seg >> 3, j = seg & 7;
                cp_async16(As + sw128((uint32_t)(m * 128 + j * 16)),
                           xb + (size_t)m * K_DIM + k0 + j * 8);
            }
        }
        cp_commit();

        // ---- compute chunk c ----
        {
            const int st = c % STAGES;
            const uint32_t As = sb32 + st * STAGE_BYTES + a_warp;
            const uint32_t Bs = sb32 + st * STAGE_BYTES + A_BYTES + b_warp;

            #pragma unroll
            for (int kk = 0; kk < 4; kk++) {
                uint32_t a[4][4];
                #pragma unroll
                for (int i = 0; i < 4; i++) {
                    uint32_t addr = As + sw128((uint32_t)(
                        (i * 16 + (lid & 15)) * 128 + kk * 32 + (lid >> 4) * 16));
                    ldmatrix4(a[i][0], a[i][1], a[i][2], a[i][3], addr);
                }
                uint32_t b[8][2];
                #pragma unroll
                for (int g = 0; g < 4; g++) {
                    int row = g * 16 + (ql >> 1) * 8 + qr;
                    int kh  = ql & 1;
                    uint32_t addr = Bs + sw128((uint32_t)(
                        row * 128 + kk * 32 + kh * 16));
                    ldmatrix4(b[2*g][0], b[2*g][1], b[2*g+1][0], b[2*g+1][1], addr);
                }
                #pragma unroll
                for (int i = 0; i < 4; i++)
                    #pragma unroll
                    for (int jn = 0; jn < 8; jn++)
                        hmma(acc[i][jn], a[i][0], a[i][1], a[i][2], a[i][3],
                             b[jn][0], b[jn][1]);
            }
        }

        // ---- deferred B dequant + STS (LDG latency hidden under the kk loop) ----
        if (fetch) {
            #pragma unroll
            for (int i = 0; i < 8; i++) {
                int n = bn + i * 16;
                uint4 q;
                q.x = dqw(bp[i].x); q.y = dqw(bp[i].y);
                q.z = dqw(bp[i].z); q.w = dqw(bp[i].w);
                *reinterpret_cast<uint4*>(sb + fB +
                    sw128((uint32_t)(n * 128 + bj * 16))) = q;
            }
        }
    }

    // ---- epilogue: scale + store fp32 ----
    #pragma unroll
    for (int i = 0; i < 4; i++) {
        int m0 = M0 + wm * 64 + i * 16 + (lid >> 2);
        #pragma unroll
        for (int j = 0; j < 8; j++) {
            int n = N0 + wn * 64 + j * 8 + 2 * (lid & 3);
            float2 s = *reinterpret_cast<const float2*>(scale + n);
            float2 o0, o1;
            o0.x = acc[i][j][0] * s.x;
            o0.y = acc[i][j][1] * s.y;
            o1.x = acc[i][j][2] * s.x;
            o1.y = acc[i][j][3] * s.y;
            *reinterpret_cast<float2*>(y + (size_t)m0 * N_DIM + n) = o0;
            *reinterpret_cast<float2*>(y + (size_t)(m0 + 8) * N_DIM + n) = o1;
        }
    }
}

// ---------------- launch ----------------
extern "C" void kernel_launch(void* const* d_in, const int* in_sizes, int n_in,
                              void* d_out, int out_size) {
    const float* x      = (const float*)d_in[0];
    const int*   packed = (const int*)  d_in[1];
    const float* scale  = (const float*)d_in[2];
    float*       y      = (float*)d_out;

    prep_kernel<<<XCONV_BLOCKS, 256>>>(x);

    static bool attr_set = false;
    if (!attr_set) {
        cudaFuncSetAttribute(qgemm_kernel,
                             cudaFuncAttributeMaxDynamicSharedMemorySize, SMEM_BYTES);
        attr_set = true;
    }
    dim3 grid(N_DIM / BN, M_DIM / BM);   // (64, 4) = 256 CTAs, 2/SM
    qgemm_kernel<<<grid, NTHREADS, SMEM_BYTES>>>(packed, scale, y);
}

// round 11
// speedup vs baseline: 1.6938x; 1.6938x over previous
#include <cuda_runtime.h>
#include <cuda_fp16.h>
#include <cstdint>

// QuantizedLinear on GB300 (sm_103a harness, compute_103 virtual arch -> legacy
// mma.sync.m16n8k16 path; tcgen05 PTX rejected by ptxas at this target).
//   y[b,o] = scale[o] * sum_k x[b,k] * (q[o,k] - 8)
//
// Round 11: R8 GEMM skeleton + in-GEMM W dequant via SMEM-RESIDENT packed B
// with SELF-OWNED segments:
//   - raw packed words cp.async'd (coalesced) into a flat smem staging buffer
//   - one chunk ahead, each thread dequants exactly the 16B segs IT loaded
//     (cp.async self-visibility after wait_group; no extra barrier, no held regs)
//   - output into a double-buffered SW128 fp16 B tile consumed by ldmatrix
// No W prepass (saves its 268 MB DRAM round trip). Prep = x->fp16 only.

static constexpr int M_DIM = 512;
static constexpr int N_DIM = 8192;
static constexpr int K_DIM = 8192;
static constexpr int KWORDS = K_DIM / 2;           // packed words per W row

static constexpr int BM = 128;
static constexpr int BN = 128;
static constexpr int KC = 64;
static constexpr int ASTAGES = 3;
static constexpr int NCHUNK = K_DIM / KC;          // 128
static constexpr int NTHREADS = 128;               // 4 warps, 2x2 of 64x64

static constexpr int A_BYTES  = BM * 128;          // 16 KB fp16 SW128
static constexpr int BP_BYTES = BN * 128;          // 16 KB packed (flat)
static constexpr int BF_BYTES = BN * 128;          // 16 KB fp16 SW128
// layout: A[3] | Bp[2] | Bf[2]
static constexpr int OFF_BP = ASTAGES * A_BYTES;            // 49152
static constexpr int OFF_BF = OFF_BP + 2 * BP_BYTES;        // 81920
static constexpr int SMEM_BYTES = OFF_BF + 2 * BF_BYTES;    // 114688 -> 2 CTAs/SM

static constexpr int XCONV_BLOCKS = (M_DIM * K_DIM / 4) / 256;   // 4096

// -------- scratch (device global; no runtime allocation) --------
__device__ __align__(16) __half g_xh[(size_t)M_DIM * K_DIM];     // 8 MB

// ---------------- helpers ----------------
__device__ __forceinline__ uint32_t smem_u32(const void* p) {
    uint32_t a;
    asm("{ .reg .u64 t; cvta.to.shared.u64 t, %1; cvt.u32.u64 %0, t; }"
        : "=r"(a) : "l"(p));
    return a;
}

__device__ __forceinline__ uint32_t sw128(uint32_t off) {
    return off ^ ((off >> 3) & 0x70u);
}

// (1024+q) - 1032 = q - 8, exact in fp16, both lanes
__device__ __forceinline__ uint32_t dq_sub(uint32_t v) {
    uint32_t r;
    asm("sub.rn.f16x2 %0, %1, %2;" : "=r"(r) : "r"(v), "r"(0x64086408u));
    return r;
}

// packed word (low byte = 2 nibbles) -> fp16x2 {low = even k (hi nibble),
// high = odd k (lo nibble)}, value q-8, exact
__device__ __forceinline__ uint32_t dqw(uint32_t w) {
    uint32_t t = ((w >> 4) & 0xFu) | 0x64006400u;
    t |= (w << 16) & 0x000F0000u;
    return dq_sub(t);
}

__device__ __forceinline__ void cp_async16(uint32_t dst, const void* src) {
    asm volatile("cp.async.cg.shared.global [%0], [%1], 16;"
                 :: "r"(dst), "l"(src) : "memory");
}
__device__ __forceinline__ void cp_commit() {
    asm volatile("cp.async.commit_group;" ::: "memory");
}
template <int N>
__device__ __forceinline__ void cp_wait() {
    asm volatile("cp.async.wait_group %0;" :: "n"(N) : "memory");
}

__device__ __forceinline__ void ldmatrix4(uint32_t& r0, uint32_t& r1,
                                          uint32_t& r2, uint32_t& r3,
                                          uint32_t addr) {
    asm volatile("ldmatrix.sync.aligned.m8n8.x4.shared.b16 {%0,%1,%2,%3}, [%4];"
                 : "=r"(r0), "=r"(r1), "=r"(r2), "=r"(r3) : "r"(addr));
}

__device__ __forceinline__ void hmma(float* d,
                                     uint32_t a0, uint32_t a1, uint32_t a2, uint32_t a3,
                                     uint32_t b0, uint32_t b1) {
    asm volatile(
        "mma.sync.aligned.m16n8k16.row.col.f32.f16.f16.f32 "
        "{%0,%1,%2,%3}, {%4,%5,%6,%7}, {%8,%9}, {%0,%1,%2,%3};"
        : "+f"(d[0]), "+f"(d[1]), "+f"(d[2]), "+f"(d[3])
        : "r"(a0), "r"(a1), "r"(a2), "r"(a3), "r"(b0), "r"(b1));
}

// ---------------- prepass: x f32 -> fp16 ----------------
__global__ void prep_kernel(const float* __restrict__ x) {
    int i = blockIdx.x * blockDim.x + threadIdx.x;      // float4 index
    float4 v = reinterpret_cast<const float4*>(x)[i];
    reinterpret_cast<__half2*>(g_xh)[2 * i + 0] = __floats2half2_rn(v.x, v.y);
    reinterpret_cast<__half2*>(g_xh)[2 * i + 1] = __floats2half2_rn(v.z, v.w);
}

// ---------------- HMMA GEMM with staged in-smem W dequant ----------------
__global__ __launch_bounds__(NTHREADS, 2)
void qgemm_kernel(const int* __restrict__ packed,
                  const float* __restrict__ scale, float* __restrict__ y) {
    extern __shared__ __align__(1024) char sb[];
    const uint32_t sb32 = smem_u32(sb);

    const int tid = threadIdx.x;
    const int wid = tid >> 5;
    const int lid = tid & 31;
    const int N0 = blockIdx.x * BN;
    const int M0 = blockIdx.y * BM;

    const int wm = wid >> 1;            // 0..1 : m offset wm*64
    const int wn = wid & 1;             // 0..1 : n offset wn*64

    const __half* xb = g_xh + (size_t)M0 * K_DIM;
    const unsigned* wpk = reinterpret_cast<const unsigned*>(packed);

    // B seg mapping: seg = tid + i*128 (i=0..7) -> n = seg>>3, j = seg&7
    // gmem 16B: row N0+n, words (k0>>1)+j*4  (8 lanes -> one 128B line)
    // Bp staging slot for seg: flat at seg*16.  Thread dequants ITS OWN segs.

    float acc[4][8][4];
    #pragma unroll
    for (int i = 0; i < 4; i++)
        #pragma unroll
        for (int j = 0; j < 8; j++)
            #pragma unroll
            for (int v = 0; v < 4; v++)
                acc[i][j][v] = 0.0f;

    // ---- prologue ----
    // g0: A[0], Bp[0]->buf0, Bp[1]->buf1 ; g1: A[1]
    {
        const uint32_t As = sb32;
        #pragma unroll
        for (int i = 0; i < 8; i++) {
            int seg = tid + i * NTHREADS;
            int m = seg >> 3, j = seg & 7;
            cp_async16(As + sw128((uint32_t)(m * 128 + j * 16)),
                       xb + (size_t)m * K_DIM + j * 8);
        }
        #pragma unroll
        for (int i = 0; i < 8; i++) {
            int seg = tid + i * NTHREADS;
            int n = seg >> 3, j = seg & 7;
            cp_async16(sb32 + OFF_BP + (uint32_t)(seg * 16),
                       wpk + (size_t)(N0 + n) * KWORDS + j * 4);
            cp_async16(sb32 + OFF_BP + BP_BYTES + (uint32_t)(seg * 16),
                       wpk + (size_t)(N0 + n) * KWORDS + (KC >> 1) + j * 4);
        }
        cp_commit();                                   // g0
        const uint32_t As1 = sb32 + A_BYTES;
        #pragma unroll
        for (int i = 0; i < 8; i++) {
            int seg = tid + i * NTHREADS;
            int m = seg >> 3, j = seg & 7;
            cp_async16(As1 + sw128((uint32_t)(m * 128 + j * 16)),
                       xb + (size_t)m * K_DIM + KC + j * 8);
        }
        cp_commit();                                   // g1
    }
    // dequant Bp[0] -> Bf[0] (own segs; visible to others at first loop sync)
    cp_wait<1>();                                      // g0 complete
    #pragma unroll
    for (int i = 0; i < 8; i++) {
        int seg = tid + i * NTHREADS;
        int n = seg >> 3, j = seg & 7;
        uint4 p = *reinterpret_cast<const uint4*>(sb + OFF_BP + seg * 16);
        uint4 q;
        q.x = dqw(p.x); q.y = dqw(p.y); q.z = dqw(p.z); q.w = dqw(p.w);
        *reinterpret_cast<uint4*>(sb + OFF_BF +
            sw128((uint32_t)(n * 128 + j * 16))) = q;
    }

    const uint32_t a_warp = (uint32_t)(wm * 64 * 128);
    const uint32_t b_warp = (uint32_t)(wn * 64 * 128);
    const int ql = lid >> 3;            // 0..3
    const int qr = lid & 7;

    for (int c = 0; c < NCHUNK; c++) {
        cp_wait<1>();
        __syncthreads();               // A[c], Bf[c%2] visible to all

        // ---- fetch A[c+2] and Bp[c+2] ----
        const int fc = c + 2;
        if (fc < NCHUNK) {
            const int k0 = fc * KC;
            const uint32_t As = sb32 + (fc % ASTAGES) * A_BYTES;
            const uint32_t Bp = sb32 + OFF_BP + (fc & 1) * BP_BYTES;
            #pragma unroll
            for (int i = 0; i < 8; i++) {
                int seg = tid + i * NTHREADS;
                int m = seg >> 3, j = seg & 7;
                cp_async16(As + sw128((uint32_t)(m * 128 + j * 16)),
                           xb + (size_t)m * K_DIM + k0 + j * 8);
            }
            #pragma unroll
            for (int i = 0; i < 8; i++) {
                int seg = tid + i * NTHREADS;
                int n = seg >> 3, j = seg & 7;
                cp_async16(Bp + (uint32_t)(seg * 16),
                           wpk + (size_t)(N0 + n) * KWORDS + (k0 >> 1) + j * 4);
            }
        }
        cp_commit();

        // ---- compute chunk c from A[c%3], Bf[c%2] ----
        {
            const uint32_t As = sb32 + (c % ASTAGES) * A_BYTES + a_warp;
            const uint32_t Bs = sb32 + OFF_BF + (c & 1) * BF_BYTES + b_warp;

            #pragma unroll
            for (int kk = 0; kk < 4; kk++) {
                uint32_t a[4][4];
                #pragma unroll
                for (int i = 0; i < 4; i++) {
                    uint32_t addr = As + sw128((uint32_t)(
                        (i * 16 + (lid & 15)) * 128 + kk * 32 + (lid >> 4) * 16));
                    ldmatrix4(a[i][0], a[i][1], a[i][2], a[i][3], addr);
                }
                uint32_t b[8][2];
                #pragma unroll
                for (int g = 0; g < 4; g++) {
                    int row = g * 16 + (ql >> 1) * 8 + qr;
                    int kh  = ql & 1;
                    uint32_t addr = Bs + sw128((uint32_t)(
                        row * 128 + kk * 32 + kh * 16));
                    ldmatrix4(b[2*g][0], b[2*g][1], b[2*g+1][0], b[2*g+1][1], addr);
                }
                #pragma unroll
                for (int i = 0; i < 4; i++)
                    #pragma unroll
                    for (int jn = 0; jn < 8; jn++)
                        hmma(acc[i][jn], a[i][0], a[i][1], a[i][2], a[i][3],
                             b[jn][0], b[jn][1]);
            }
        }

        // ---- dequant Bp[c+1] -> Bf[(c+1)%2] (own segs only) ----
        if (c + 1 < NCHUNK) {
            cp_wait<1>();              // group carrying Bp[c+1] (iter c-1 / g0) done
            const char* src = sb + OFF_BP + ((c + 1) & 1) * BP_BYTES;
            char*       dst = sb + OFF_BF + ((c + 1) & 1) * BF_BYTES;
            #pragma unroll
            for (int i = 0; i < 8; i++) {
                int seg = tid + i * NTHREADS;
                int n = seg >> 3, j = seg & 7;
                uint4 p = *reinterpret_cast<const uint4*>(src + seg * 16);
                uint4 q;
                q.x = dqw(p.x); q.y = dqw(p.y); q.z = dqw(p.z); q.w = dqw(p.w);
                *reinterpret_cast<uint4*>(dst +
                    sw128((uint32_t)(n * 128 + j * 16))) = q;
            }
        }
    }

    // ---- epilogue: scale + store fp32 ----
    #pragma unroll
    for (int i = 0; i < 4; i++) {
        int m0 = M0 + wm * 64 + i * 16 + (lid >> 2);
        #pragma unroll
        for (int j = 0; j < 8; j++) {
            int n = N0 + wn * 64 + j * 8 + 2 * (lid & 3);
            float2 s = *reinterpret_cast<const float2*>(scale + n);
            float2 o0, o1;
            o0.x = acc[i][j][0] * s.x;
            o0.y = acc[i][j][1] * s.y;
            o1.x = acc[i][j][2] * s.x;
            o1.y = acc[i][j][3] * s.y;
            *reinterpret_cast<float2*>(y + (size_t)m0 * N_DIM + n) = o0;
            *reinterpret_cast<float2*>(y + (size_t)(m0 + 8) * N_DIM + n) = o1;
        }
    }
}

// ---------------- launch ----------------
extern "C" void kernel_launch(void* const* d_in, const int* in_sizes, int n_in,
                              void* d_out, int out_size) {
    const float* x      = (const float*)d_in[0];
    const int*   packed = (const int*)  d_in[1];
    const float* scale  = (const float*)d_in[2];
    float*       y      = (float*)d_out;

    prep_kernel<<<XCONV_BLOCKS, 256>>>(x);

    static bool attr_set = false;
    if (!attr_set) {
        cudaFuncSetAttribute(qgemm_kernel,
                             cudaFuncAttributeMaxDynamicSharedMemorySize, SMEM_BYTES);
        attr_set = true;
    }
    dim3 grid(N_DIM / BN, M_DIM / BM);   // (64, 4) = 256 CTAs, 2/SM
    qgemm_kernel<<<grid, NTHREADS, SMEM_BYTES>>>(packed, scale, y);
}